// round 4
// baseline (speedup 1.0000x reference)
#include <cuda_runtime.h>

#define H 256
#define P_PATHS 32768
#define LMAX 16
#define KDIM 288          // 256 path_emb + 8 edge + 16 scalar + 8 zero pad
#define NSTAGES (KDIM / 8)

// ---------------- scratch (no allocations allowed) ----------------
__device__ __align__(128) float g_A[(size_t)P_PATHS * KDIM];   // ~37.7 MB
__device__ __align__(128) float g_Wf[KDIM * H];                // packed W1 tail
__device__ __align__(128) float g_cpart[8][H];                 // partial src/dst+b1 contribution

// ---------------- packed f32x2 helpers (sm_103a FFMA2 path) ----------------
typedef unsigned long long u64;
__device__ __forceinline__ u64 pack2(float x, float y) {
    u64 r; asm("mov.b64 %0, {%1, %2};" : "=l"(r) : "f"(x), "f"(y)); return r;
}
__device__ __forceinline__ void unpack2(u64 v, float& x, float& y) {
    asm("mov.b64 {%0, %1}, %2;" : "=f"(x), "=f"(y) : "l"(v));
}
__device__ __forceinline__ void ffma2(u64& d, u64 a, u64 b) {
    asm("fma.rn.f32x2 %0, %1, %2, %0;" : "+l"(d) : "l"(a), "l"(b));
}

// ---------------- kernel 1: repack W1 rows used by the per-path GEMM ----------------
// fused layout: [src 0:256 | dst 256:512 | path_emb 512:768 | edge 768:776 | scalar 776:792]
__global__ void pack_wf_kernel(const float* __restrict__ W1) {
    int k = blockIdx.x;      // 0..287
    int j = threadIdx.x;     // 0..255
    float v = 0.f;
    if (k < 256)       v = W1[(512 + k) * H + j];
    else if (k < 264)  v = W1[(768 + (k - 256)) * H + j];
    else if (k < 280)  v = W1[(776 + (k - 264)) * H + j];
    g_Wf[k * H + j] = v;
}

// ---------------- kernel 2: constant contribution c = b1 + src@W1[0:256] + dst@W1[256:512] ----------------
__global__ void compute_c_kernel(const float* __restrict__ node_embs,
                                 const float* __restrict__ W1,
                                 const float* __restrict__ b1,
                                 const int* __restrict__ src_idx,
                                 const int* __restrict__ dst_idx) {
    int b = blockIdx.x;      // 0..7 : k slice [b*32, b*32+32)
    int j = threadIdx.x;     // 0..255
    const float* s = node_embs + (long)(*src_idx) * H;
    const float* d = node_embs + (long)(*dst_idx) * H;
    float acc = (b == 0) ? b1[j] : 0.f;
    int k0 = b * 32;
#pragma unroll 8
    for (int k = k0; k < k0 + 32; k++) {
        acc = fmaf(s[k], W1[k * H + j], acc);
        acc = fmaf(d[k], W1[(256 + k) * H + j], acc);
    }
    g_cpart[b][j] = acc;
}

// ---------------- kernel 3: ragged gather-mean + feature concat into A[P, 288] ----------------
__global__ void gather_kernel(const float* __restrict__ node_embs,
                              const int* __restrict__ path_nodes,
                              const int* __restrict__ path_lens,
                              const float* __restrict__ edge_feats,
                              const float* __restrict__ scalar_feats) {
    int p = blockIdx.x;
    int t = threadIdx.x;
    int len = path_lens[p];
    const int* nodes = path_nodes + p * LMAX;

    // Preload all 16 indices (always valid memory) to expose MLP on the row gathers.
    int idx[LMAX];
#pragma unroll
    for (int l = 0; l < LMAX; l++) idx[l] = nodes[l];

    float acc = 0.f;
#pragma unroll 4
    for (int l = 0; l < len; l++) {
        acc += node_embs[(long)idx[l] * H + t];
    }
    float inv = 1.f / (float)max(len, 1);
    g_A[(size_t)p * KDIM + t] = acc * inv;

    if (t < 32) {
        float v = 0.f;
        if (t < 8)       v = edge_feats[p * 8 + t];
        else if (t < 24) v = scalar_feats[p * 16 + (t - 8)];
        g_A[(size_t)p * KDIM + 256 + t] = v;   // cols 280..287 stay 0
    }
}

// ---------------- kernel 4: fused GEMM (A[128x288] @ Wf[288x256]) + relu + dot(W2) + b2 + mask ----------------
__global__ __launch_bounds__(256, 2)
void mlp_kernel(const int* __restrict__ path_lens,
                const float* __restrict__ W2,
                const float* __restrict__ b2,
                float* __restrict__ out) {
    __shared__ __align__(16) float As[2][8][132];   // [buf][k][m], padded row
    __shared__ __align__(16) float Bs[2][8][128];   // [buf][k][n-half]
    __shared__ float cs[H];
    __shared__ float w2s[H];
    __shared__ float qp[128][17];                   // per-path partial q, padded

    int t  = threadIdx.x;
    int tx = t & 15, ty = t >> 4;
    int row = ty * 8, col = tx * 8;
    int p0  = blockIdx.x * 128;

    // constants
    {
        float cv = 0.f;
#pragma unroll
        for (int b = 0; b < 8; b++) cv += g_cpart[b][t];
        cs[t]  = cv;
        w2s[t] = W2[t];
    }
    for (int i = t; i < 128 * 17; i += 256) (&qp[0][0])[i] = 0.f;
    __syncthreads();

    // load mappings
    int ar = t >> 1;            // A tile row 0..127
    int ak = (t & 1) * 4;       // A k sub-offset {0,4}
    int bk = t >> 5;            // B k row 0..7
    int bc = (t & 31) * 4;      // B col offset

    const float* Abase = &g_A[(size_t)(p0 + ar) * KDIM + ak];

    for (int nh = 0; nh < 2; nh++) {
        int n0 = nh * 128;
        u64 acc[8][4];
#pragma unroll
        for (int i = 0; i < 8; i++)
#pragma unroll
            for (int j = 0; j < 4; j++) acc[i][j] = 0ull;

        // prologue: stage 0
        float4 pa = *(const float4*)(Abase + 0);
        float4 pb = *(const float4*)&g_Wf[(0 + bk) * H + n0 + bc];
        As[0][ak + 0][ar] = pa.x;
        As[0][ak + 1][ar] = pa.y;
        As[0][ak + 2][ar] = pa.z;
        As[0][ak + 3][ar] = pa.w;
        *(float4*)&Bs[0][bk][bc] = pb;
        __syncthreads();

        for (int s = 0; s < NSTAGES; s++) {
            int buf = s & 1;
            if (s + 1 < NSTAGES) {
                pa = *(const float4*)(Abase + (s + 1) * 8);
                pb = *(const float4*)&g_Wf[((s + 1) * 8 + bk) * H + n0 + bc];
            }
#pragma unroll
            for (int kk = 0; kk < 8; kk++) {
                float4 a0 = *(const float4*)&As[buf][kk][row];
                float4 a1 = *(const float4*)&As[buf][kk][row + 4];
                const u64* bp = (const u64*)&Bs[buf][kk][col];
                u64 bv0 = bp[0], bv1 = bp[1], bv2 = bp[2], bv3 = bp[3];
                float a[8] = {a0.x, a0.y, a0.z, a0.w, a1.x, a1.y, a1.z, a1.w};
#pragma unroll
                for (int i = 0; i < 8; i++) {
                    u64 ad = pack2(a[i], a[i]);
                    ffma2(acc[i][0], ad, bv0);
                    ffma2(acc[i][1], ad, bv1);
                    ffma2(acc[i][2], ad, bv2);
                    ffma2(acc[i][3], ad, bv3);
                }
            }
            if (s + 1 < NSTAGES) {
                int nb = buf ^ 1;
                As[nb][ak + 0][ar] = pa.x;
                As[nb][ak + 1][ar] = pa.y;
                As[nb][ak + 2][ar] = pa.z;
                As[nb][ak + 3][ar] = pa.w;
                *(float4*)&Bs[nb][bk][bc] = pb;
                __syncthreads();
            }
        }

        // epilogue for this n-half: +c, relu, dot W2
#pragma unroll
        for (int i = 0; i < 8; i++) {
            float si = 0.f;
#pragma unroll
            for (int j = 0; j < 4; j++) {
                float v0, v1;
                unpack2(acc[i][j], v0, v1);
                int jg = n0 + col + 2 * j;
                v0 = fmaxf(v0 + cs[jg],     0.f);
                v1 = fmaxf(v1 + cs[jg + 1], 0.f);
                si = fmaf(v0, w2s[jg],     si);
                si = fmaf(v1, w2s[jg + 1], si);
            }
            qp[row + i][tx] += si;   // (m, tx) cell is exclusively owned -> deterministic
        }
    }
    __syncthreads();

    if (t < 128) {
        int p = p0 + t;
        float s = b2[0];
#pragma unroll
        for (int j = 0; j < 16; j++) s += qp[t][j];
        out[p] = (path_lens[p] > 0) ? s : 0.f;
    }
}

// ---------------- launch ----------------
extern "C" void kernel_launch(void* const* d_in, const int* in_sizes, int n_in,
                              void* d_out, int out_size) {
    const float* node_embs    = (const float*)d_in[0];
    const int*   path_nodes   = (const int*)  d_in[1];
    const int*   path_lens    = (const int*)  d_in[2];
    const float* edge_feats   = (const float*)d_in[3];
    const float* scalar_feats = (const float*)d_in[4];
    const float* W1           = (const float*)d_in[5];
    const float* b1           = (const float*)d_in[6];
    const float* W2           = (const float*)d_in[7];
    const float* b2           = (const float*)d_in[8];
    const int*   src_idx      = (const int*)  d_in[9];
    const int*   dst_idx      = (const int*)  d_in[10];
    float* out = (float*)d_out;

    pack_wf_kernel<<<KDIM, H>>>(W1);
    compute_c_kernel<<<8, H>>>(node_embs, W1, b1, src_idx, dst_idx);
    gather_kernel<<<P_PATHS, H>>>(node_embs, path_nodes, path_lens, edge_feats, scalar_feats);
    mlp_kernel<<<P_PATHS / 128, 256>>>(path_lens, W2, b2, out);
}

// round 5
// speedup vs baseline: 1.0038x; 1.0038x over previous
#include <cuda_runtime.h>

#define H 256
#define P_PATHS 32768
#define LMAX 16
#define KDIM 288          // 256 path_emb + 8 edge + 16 scalar + 8 zero pad
#define NSTAGES (KDIM / 8)

// ---------------- scratch (no allocations allowed) ----------------
__device__ __align__(128) float g_A[(size_t)P_PATHS * KDIM];   // ~37.7 MB
__device__ __align__(128) float g_Wf[KDIM * H];                // packed W1 tail
__device__ __align__(128) float g_cpart[8][H];                 // partial src/dst+b1 contribution

// ---------------- packed f32x2 helpers (sm_103a FFMA2 path) ----------------
typedef unsigned long long u64;
__device__ __forceinline__ u64 pack2(float x, float y) {
    u64 r; asm("mov.b64 %0, {%1, %2};" : "=l"(r) : "f"(x), "f"(y)); return r;
}
__device__ __forceinline__ void unpack2(u64 v, float& x, float& y) {
    asm("mov.b64 {%0, %1}, %2;" : "=f"(x), "=f"(y) : "l"(v));
}
__device__ __forceinline__ void ffma2(u64& d, u64 a, u64 b) {
    asm("fma.rn.f32x2 %0, %1, %2, %0;" : "+l"(d) : "l"(a), "l"(b));
}

// ---------------- kernel 1: repack W1 rows used by the per-path GEMM ----------------
// fused layout: [src 0:256 | dst 256:512 | path_emb 512:768 | edge 768:776 | scalar 776:792]
__global__ void pack_wf_kernel(const float* __restrict__ W1) {
    int k = blockIdx.x;      // 0..287
    int j = threadIdx.x;     // 0..255
    float v = 0.f;
    if (k < 256)       v = W1[(512 + k) * H + j];
    else if (k < 264)  v = W1[(768 + (k - 256)) * H + j];
    else if (k < 280)  v = W1[(776 + (k - 264)) * H + j];
    g_Wf[k * H + j] = v;
}

// ---------------- kernel 2: constant contribution c = b1 + src@W1[0:256] + dst@W1[256:512] ----------------
__global__ void compute_c_kernel(const float* __restrict__ node_embs,
                                 const float* __restrict__ W1,
                                 const float* __restrict__ b1,
                                 const int* __restrict__ src_idx,
                                 const int* __restrict__ dst_idx) {
    int b = blockIdx.x;      // 0..7 : k slice [b*32, b*32+32)
    int j = threadIdx.x;     // 0..255
    const float* s = node_embs + (long)(*src_idx) * H;
    const float* d = node_embs + (long)(*dst_idx) * H;
    float acc = (b == 0) ? b1[j] : 0.f;
    int k0 = b * 32;
#pragma unroll 8
    for (int k = k0; k < k0 + 32; k++) {
        acc = fmaf(s[k], W1[k * H + j], acc);
        acc = fmaf(d[k], W1[(256 + k) * H + j], acc);
    }
    g_cpart[b][j] = acc;
}

// ---------------- kernel 3: ragged gather-mean + feature concat into A[P, 288] ----------------
__global__ void gather_kernel(const float* __restrict__ node_embs,
                              const int* __restrict__ path_nodes,
                              const int* __restrict__ path_lens,
                              const float* __restrict__ edge_feats,
                              const float* __restrict__ scalar_feats) {
    int p = blockIdx.x;
    int t = threadIdx.x;
    int len = path_lens[p];
    const int* nodes = path_nodes + p * LMAX;

    // Preload all 16 indices (always valid memory) to expose MLP on the row gathers.
    int idx[LMAX];
#pragma unroll
    for (int l = 0; l < LMAX; l++) idx[l] = nodes[l];

    float acc = 0.f;
#pragma unroll 4
    for (int l = 0; l < len; l++) {
        acc += node_embs[(long)idx[l] * H + t];
    }
    float inv = 1.f / (float)max(len, 1);
    g_A[(size_t)p * KDIM + t] = acc * inv;

    if (t < 32) {
        float v = 0.f;
        if (t < 8)       v = edge_feats[p * 8 + t];
        else if (t < 24) v = scalar_feats[p * 16 + (t - 8)];
        g_A[(size_t)p * KDIM + 256 + t] = v;   // cols 280..287 stay 0
    }
}

// ---------------- kernel 4: fused GEMM (A[128x288] @ Wf[288x256]) + relu + dot(W2) + b2 + mask ----------------
__global__ __launch_bounds__(256, 2)
void mlp_kernel(const int* __restrict__ path_lens,
                const float* __restrict__ W2,
                const float* __restrict__ b2,
                float* __restrict__ out) {
    __shared__ __align__(16) float As[2][8][132];   // [buf][k][m], padded row
    __shared__ __align__(16) float Bs[2][8][128];   // [buf][k][n-half]
    __shared__ float cs[H];
    __shared__ float w2s[H];
    __shared__ float qp[128][17];                   // per-path partial q, padded

    int t  = threadIdx.x;
    int tx = t & 15, ty = t >> 4;
    int row = ty * 8, col = tx * 8;
    int p0  = blockIdx.x * 128;

    // constants
    {
        float cv = 0.f;
#pragma unroll
        for (int b = 0; b < 8; b++) cv += g_cpart[b][t];
        cs[t]  = cv;
        w2s[t] = W2[t];
    }
    for (int i = t; i < 128 * 17; i += 256) (&qp[0][0])[i] = 0.f;
    __syncthreads();

    // load mappings
    int ar = t >> 1;            // A tile row 0..127
    int ak = (t & 1) * 4;       // A k sub-offset {0,4}
    int bk = t >> 5;            // B k row 0..7
    int bc = (t & 31) * 4;      // B col offset

    const float* Abase = &g_A[(size_t)(p0 + ar) * KDIM + ak];

    for (int nh = 0; nh < 2; nh++) {
        int n0 = nh * 128;
        u64 acc[8][4];
#pragma unroll
        for (int i = 0; i < 8; i++)
#pragma unroll
            for (int j = 0; j < 4; j++) acc[i][j] = 0ull;

        // prologue: stage 0
        float4 pa = *(const float4*)(Abase + 0);
        float4 pb = *(const float4*)&g_Wf[(0 + bk) * H + n0 + bc];
        As[0][ak + 0][ar] = pa.x;
        As[0][ak + 1][ar] = pa.y;
        As[0][ak + 2][ar] = pa.z;
        As[0][ak + 3][ar] = pa.w;
        *(float4*)&Bs[0][bk][bc] = pb;
        __syncthreads();

        for (int s = 0; s < NSTAGES; s++) {
            int buf = s & 1;
            if (s + 1 < NSTAGES) {
                pa = *(const float4*)(Abase + (s + 1) * 8);
                pb = *(const float4*)&g_Wf[((s + 1) * 8 + bk) * H + n0 + bc];
            }
#pragma unroll
            for (int kk = 0; kk < 8; kk++) {
                float4 a0 = *(const float4*)&As[buf][kk][row];
                float4 a1 = *(const float4*)&As[buf][kk][row + 4];
                const u64* bp = (const u64*)&Bs[buf][kk][col];
                u64 bv0 = bp[0], bv1 = bp[1], bv2 = bp[2], bv3 = bp[3];
                float a[8] = {a0.x, a0.y, a0.z, a0.w, a1.x, a1.y, a1.z, a1.w};
#pragma unroll
                for (int i = 0; i < 8; i++) {
                    u64 ad = pack2(a[i], a[i]);
                    ffma2(acc[i][0], ad, bv0);
                    ffma2(acc[i][1], ad, bv1);
                    ffma2(acc[i][2], ad, bv2);
                    ffma2(acc[i][3], ad, bv3);
                }
            }
            if (s + 1 < NSTAGES) {
                int nb = buf ^ 1;
                As[nb][ak + 0][ar] = pa.x;
                As[nb][ak + 1][ar] = pa.y;
                As[nb][ak + 2][ar] = pa.z;
                As[nb][ak + 3][ar] = pa.w;
                *(float4*)&Bs[nb][bk][bc] = pb;
                __syncthreads();
            }
        }

        // epilogue for this n-half: +c, relu, dot W2
#pragma unroll
        for (int i = 0; i < 8; i++) {
            float si = 0.f;
#pragma unroll
            for (int j = 0; j < 4; j++) {
                float v0, v1;
                unpack2(acc[i][j], v0, v1);
                int jg = n0 + col + 2 * j;
                v0 = fmaxf(v0 + cs[jg],     0.f);
                v1 = fmaxf(v1 + cs[jg + 1], 0.f);
                si = fmaf(v0, w2s[jg],     si);
                si = fmaf(v1, w2s[jg + 1], si);
            }
            qp[row + i][tx] += si;   // (m, tx) cell is exclusively owned -> deterministic
        }
    }
    __syncthreads();

    if (t < 128) {
        int p = p0 + t;
        float s = b2[0];
#pragma unroll
        for (int j = 0; j < 16; j++) s += qp[t][j];
        out[p] = (path_lens[p] > 0) ? s : 0.f;
    }
}

// ---------------- launch ----------------
extern "C" void kernel_launch(void* const* d_in, const int* in_sizes, int n_in,
                              void* d_out, int out_size) {
    const float* node_embs    = (const float*)d_in[0];
    const int*   path_nodes   = (const int*)  d_in[1];
    const int*   path_lens    = (const int*)  d_in[2];
    const float* edge_feats   = (const float*)d_in[3];
    const float* scalar_feats = (const float*)d_in[4];
    const float* W1           = (const float*)d_in[5];
    const float* b1           = (const float*)d_in[6];
    const float* W2           = (const float*)d_in[7];
    const float* b2           = (const float*)d_in[8];
    const int*   src_idx      = (const int*)  d_in[9];
    const int*   dst_idx      = (const int*)  d_in[10];
    float* out = (float*)d_out;

    pack_wf_kernel<<<KDIM, H>>>(W1);
    compute_c_kernel<<<8, H>>>(node_embs, W1, b1, src_idx, dst_idx);
    gather_kernel<<<P_PATHS, H>>>(node_embs, path_nodes, path_lens, edge_feats, scalar_feats);
    mlp_kernel<<<P_PATHS / 128, 256>>>(path_lens, W2, b2, out);
}

// round 6
// speedup vs baseline: 1.3078x; 1.3029x over previous
#include <cuda_runtime.h>

#define H 256
#define P_PATHS 32768
#define LMAX 16
#define KDIM 288          // 256 path_emb + 8 edge + 16 scalar + 8 zero pad
#define NSTAGES 36        // KDIM / 8
#define MTILE 64          // paths per block
#define ASTRIDE 68        // As row stride in floats (68 % 32 == 4, 68*4 % 16 == 0)

// ---------------- persistent scratch (no allocations allowed) ----------------
__device__ __align__(128) float g_Wf[KDIM * H];     // packed W1 tail (k-major, zero-padded)
__device__ __align__(128) float g_cpart[8][H];      // partial src/dst + b1 contribution

// ---------------- packed f32x2 helpers (sm_103a FFMA2 path) ----------------
typedef unsigned long long u64;
__device__ __forceinline__ u64 pack2(float x, float y) {
    u64 r; asm("mov.b64 %0, {%1, %2};" : "=l"(r) : "f"(x), "f"(y)); return r;
}
__device__ __forceinline__ void unpack2(u64 v, float& x, float& y) {
    asm("mov.b64 {%0, %1}, %2;" : "=f"(x), "=f"(y) : "l"(v));
}
__device__ __forceinline__ void ffma2(u64& d, u64 a, u64 b) {
    asm("fma.rn.f32x2 %0, %1, %2, %0;" : "+l"(d) : "l"(a), "l"(b));
}

// ---------------- kernel 1: repack W1 rows used by the per-path GEMM ----------------
// fused layout: [src 0:256 | dst 256:512 | path_emb 512:768 | edge 768:776 | scalar 776:792]
__global__ void pack_wf_kernel(const float* __restrict__ W1) {
    int k = blockIdx.x;      // 0..287
    int j = threadIdx.x;     // 0..255
    float v = 0.f;
    if (k < 256)       v = W1[(512 + k) * H + j];
    else if (k < 264)  v = W1[(768 + (k - 256)) * H + j];
    else if (k < 280)  v = W1[(776 + (k - 264)) * H + j];
    g_Wf[k * H + j] = v;
}

// ---------------- kernel 2: c = b1 + src@W1[0:256] + dst@W1[256:512] (8 partials) ----------------
__global__ void compute_c_kernel(const float* __restrict__ node_embs,
                                 const float* __restrict__ W1,
                                 const float* __restrict__ b1,
                                 const int* __restrict__ src_idx,
                                 const int* __restrict__ dst_idx) {
    int b = blockIdx.x;      // 0..7 : k slice [b*32, b*32+32)
    int j = threadIdx.x;     // 0..255
    const float* s = node_embs + (long)(*src_idx) * H;
    const float* d = node_embs + (long)(*dst_idx) * H;
    float acc = (b == 0) ? b1[j] : 0.f;
    int k0 = b * 32;
#pragma unroll 8
    for (int k = k0; k < k0 + 32; k++) {
        acc = fmaf(s[k], W1[k * H + j], acc);
        acc = fmaf(d[k], W1[(256 + k) * H + j], acc);
    }
    g_cpart[b][j] = acc;
}

// ---------------- kernel 3: FUSED gather-mean + GEMM + relu + dot(W2) + mask ----------------
// Block: 64 paths x 256 outputs. 256 threads.
// Phase 1: gather ragged means directly into shared A-tile (k-major).
// Phase 2: GEMM from shared A (resident) x B (double-buffered from g_Wf),
//          warp tile 32x64 so A-reads are broadcast (1 phase) and B-reads 2 phases.
__global__ __launch_bounds__(256, 2)
void fused_kernel(const float* __restrict__ node_embs,
                  const int*   __restrict__ path_nodes,
                  const int*   __restrict__ path_lens,
                  const float* __restrict__ edge_feats,
                  const float* __restrict__ scalar_feats,
                  const float* __restrict__ W2,
                  const float* __restrict__ b2,
                  float*       __restrict__ out) {
    extern __shared__ float sm[];
    float* As  = sm;                           // [KDIM][ASTRIDE]   78336 B
    float* Bs  = As + KDIM * ASTRIDE;          // [2][8][256]       16384 B
    float* cs  = Bs + 2 * 8 * H;               // [256]
    float* w2s = cs + H;                       // [256]
    float* qp  = w2s + H;                      // [64][33]          8448 B

    int t  = threadIdx.x;
    int p0 = blockIdx.x * MTILE;

    // constants into shared
    {
        float cv = 0.f;
#pragma unroll
        for (int b = 0; b < 8; b++) cv += g_cpart[b][t];
        cs[t]  = cv;
        w2s[t] = W2[t];
    }

    // ---- Phase 1: gather (4 threads per path, 64 h-cols each) ----
    {
        int pth = t >> 2, hq = t & 3;
        int p   = p0 + pth;
        int len = path_lens[p];
        const int* nodes = path_nodes + p * LMAX;

        float4 a[16];
#pragma unroll
        for (int c = 0; c < 16; c++) a[c] = make_float4(0.f, 0.f, 0.f, 0.f);

#pragma unroll
        for (int l = 0; l < LMAX; l++) {
            if (l < len) {
                int id = nodes[l];
                const float4* r = (const float4*)(node_embs + (size_t)id * H) + hq * 16;
#pragma unroll
                for (int c = 0; c < 16; c++) {
                    float4 v = r[c];
                    a[c].x += v.x; a[c].y += v.y; a[c].z += v.z; a[c].w += v.w;
                }
            }
        }
        float inv = 1.f / (float)max(len, 1);
        int hb = hq * 64;
#pragma unroll
        for (int c = 0; c < 16; c++) {
            As[(hb + 4 * c + 0) * ASTRIDE + pth] = a[c].x * inv;
            As[(hb + 4 * c + 1) * ASTRIDE + pth] = a[c].y * inv;
            As[(hb + 4 * c + 2) * ASTRIDE + pth] = a[c].z * inv;
            As[(hb + 4 * c + 3) * ASTRIDE + pth] = a[c].w * inv;
        }
    }
    // edge/scalar features + zero pad rows (cols 256..287 of A)
    if (t < MTILE) {
        int p = p0 + t;
#pragma unroll
        for (int e = 0; e < 8; e++)  As[(256 + e) * ASTRIDE + t] = edge_feats[p * 8 + e];
#pragma unroll
        for (int f = 0; f < 16; f++) As[(264 + f) * ASTRIDE + t] = scalar_feats[p * 16 + f];
#pragma unroll
        for (int z = 0; z < 8; z++)  As[(280 + z) * ASTRIDE + t] = 0.f;
    }

    // ---- B prologue: stage 0 (8 k-rows x 256 cols = 512 float4, 2 per thread) ----
    const float4* Wf4 = (const float4*)g_Wf;
    float4* Bs4 = (float4*)Bs;
    int f0 = 2 * t, f1 = 2 * t + 1;
    {
        float4 q0 = Wf4[f0], q1 = Wf4[f1];
        Bs4[f0] = q0; Bs4[f1] = q1;
    }
    __syncthreads();   // covers As + Bs[0]

    // ---- Phase 2: GEMM. Warp tile 32x64, micro-tile 8x8 per thread ----
    int w = t >> 5, lane = t & 31;
    int row = ((w & 1) << 5) + ((lane & 3) << 3);          // 0..56
    int col = ((w >> 1) << 6) + ((lane >> 2) << 3);        // 0..248

    u64 acc[8][4];
#pragma unroll
    for (int i = 0; i < 8; i++)
#pragma unroll
        for (int j = 0; j < 4; j++) acc[i][j] = 0ull;

    float4 pb0, pb1;
    for (int s = 0; s < NSTAGES; s++) {
        int buf = s & 1;
        if (s + 1 < NSTAGES) {
            pb0 = Wf4[(s + 1) * 512 + f0];
            pb1 = Wf4[(s + 1) * 512 + f1];
        }
        const float* Bbuf = Bs + buf * (8 * H);
#pragma unroll
        for (int kk = 0; kk < 8; kk++) {
            int kg = s * 8 + kk;
            float4 a0 = *(const float4*)&As[kg * ASTRIDE + row];       // broadcast, 1 phase
            float4 a1 = *(const float4*)&As[kg * ASTRIDE + row + 4];
            ulonglong2 bA = *(const ulonglong2*)&Bbuf[kk * H + col];   // 2 phases
            ulonglong2 bB = *(const ulonglong2*)&Bbuf[kk * H + col + 4];
            float av[8] = {a0.x, a0.y, a0.z, a0.w, a1.x, a1.y, a1.z, a1.w};
#pragma unroll
            for (int i = 0; i < 8; i++) {
                u64 ad = pack2(av[i], av[i]);
                ffma2(acc[i][0], ad, bA.x);
                ffma2(acc[i][1], ad, bA.y);
                ffma2(acc[i][2], ad, bB.x);
                ffma2(acc[i][3], ad, bB.y);
            }
        }
        if (s + 1 < NSTAGES) {
            Bs4[(buf ^ 1) * 512 + f0] = pb0;
            Bs4[(buf ^ 1) * 512 + f1] = pb1;
            __syncthreads();
        }
    }

    // ---- epilogue: +c, relu, dot(W2) partials ----
    int cgrp = col >> 3;   // 0..31, (row,cgrp) uniquely owned
#pragma unroll
    for (int i = 0; i < 8; i++) {
        float si = 0.f;
#pragma unroll
        for (int j = 0; j < 4; j++) {
            float v0, v1;
            unpack2(acc[i][j], v0, v1);
            int jg = col + 2 * j;
            v0 = fmaxf(v0 + cs[jg],     0.f);
            v1 = fmaxf(v1 + cs[jg + 1], 0.f);
            si = fmaf(v0, w2s[jg],     si);
            si = fmaf(v1, w2s[jg + 1], si);
        }
        qp[(row + i) * 33 + cgrp] = si;
    }
    __syncthreads();

    if (t < MTILE) {
        float s = b2[0];
#pragma unroll
        for (int j = 0; j < 32; j++) s += qp[t * 33 + j];
        int p = p0 + t;
        out[p] = (path_lens[p] > 0) ? s : 0.f;
    }
}

// ---------------- launch ----------------
#define FUSED_SMEM ((KDIM * ASTRIDE + 2 * 8 * H + H + H + 64 * 33) * (int)sizeof(float))

extern "C" void kernel_launch(void* const* d_in, const int* in_sizes, int n_in,
                              void* d_out, int out_size) {
    const float* node_embs    = (const float*)d_in[0];
    const int*   path_nodes   = (const int*)  d_in[1];
    const int*   path_lens    = (const int*)  d_in[2];
    const float* edge_feats   = (const float*)d_in[3];
    const float* scalar_feats = (const float*)d_in[4];
    const float* W1           = (const float*)d_in[5];
    const float* b1           = (const float*)d_in[6];
    const float* W2           = (const float*)d_in[7];
    const float* b2           = (const float*)d_in[8];
    const int*   src_idx      = (const int*)  d_in[9];
    const int*   dst_idx      = (const int*)  d_in[10];
    float* out = (float*)d_out;

    cudaFuncSetAttribute(fused_kernel,
                         cudaFuncAttributeMaxDynamicSharedMemorySize, FUSED_SMEM);

    pack_wf_kernel<<<KDIM, H>>>(W1);
    compute_c_kernel<<<8, H>>>(node_embs, W1, b1, src_idx, dst_idx);
    fused_kernel<<<P_PATHS / MTILE, 256, FUSED_SMEM>>>(
        node_embs, path_nodes, path_lens, edge_feats, scalar_feats, W2, b2, out);
}

// round 7
// speedup vs baseline: 1.7878x; 1.3670x over previous
#include <cuda_runtime.h>

#define H 256
#define P_PATHS 32768
#define LMAX 16
#define KDIM 288          // 256 path_emb + 8 edge + 16 scalar + 8 zero pad
#define NSTAGES 36        // KDIM / 8
#define MTILE 64          // paths per block
#define ASTRIDE 68        // As row stride in floats (mult of 4 for float4 alignment)

// ---------------- persistent scratch (no allocations allowed) ----------------
__device__ __align__(128) float g_Wf[KDIM * H];     // packed W1 tail (k-major, zero-padded)
__device__ __align__(128) float g_cpart[8][H];      // partial src/dst + b1 contribution

// ---------------- packed f32x2 helpers (sm_103a FFMA2 path) ----------------
typedef unsigned long long u64;
__device__ __forceinline__ u64 pack2(float x, float y) {
    u64 r; asm("mov.b64 %0, {%1, %2};" : "=l"(r) : "f"(x), "f"(y)); return r;
}
__device__ __forceinline__ void unpack2(u64 v, float& x, float& y) {
    asm("mov.b64 {%0, %1}, %2;" : "=f"(x), "=f"(y) : "l"(v));
}
__device__ __forceinline__ void ffma2(u64& d, u64 a, u64 b) {
    asm("fma.rn.f32x2 %0, %1, %2, %0;" : "+l"(d) : "l"(a), "l"(b));
}

// bank swizzle for the k-major A tile: permutes 4-column groups per 8-k block
__device__ __forceinline__ int swz(int k) { return ((k >> 3) & 7) << 2; }

// ---------------- kernel 1: prep = pack Wf + compute c partials ----------------
// fused layout: [src 0:256 | dst 256:512 | path_emb 512:768 | edge 768:776 | scalar 776:792]
__global__ void prep_kernel(const float* __restrict__ W1,
                            const float* __restrict__ node_embs,
                            const float* __restrict__ b1,
                            const int* __restrict__ src_idx,
                            const int* __restrict__ dst_idx) {
    int bid = blockIdx.x;
    int j = threadIdx.x;     // 0..255
    if (bid < KDIM) {
        int k = bid;
        float v = 0.f;
        if (k < 256)       v = W1[(512 + k) * H + j];
        else if (k < 264)  v = W1[(768 + (k - 256)) * H + j];
        else if (k < 280)  v = W1[(776 + (k - 264)) * H + j];
        g_Wf[k * H + j] = v;
    } else {
        int b = bid - KDIM;  // 0..7 : k slice [b*32, b*32+32)
        const float* s = node_embs + (long)(*src_idx) * H;
        const float* d = node_embs + (long)(*dst_idx) * H;
        float acc = (b == 0) ? b1[j] : 0.f;
        int k0 = b * 32;
#pragma unroll 8
        for (int k = k0; k < k0 + 32; k++) {
            acc = fmaf(s[k], W1[k * H + j], acc);
            acc = fmaf(d[k], W1[(256 + k) * H + j], acc);
        }
        g_cpart[b][j] = acc;
    }
}

// ---------------- kernel 2: FUSED gather-mean + GEMM + relu + dot(W2) + mask ----------------
__global__ __launch_bounds__(256, 2)
void fused_kernel(const float* __restrict__ node_embs,
                  const int*   __restrict__ path_nodes,
                  const int*   __restrict__ path_lens,
                  const float* __restrict__ edge_feats,
                  const float* __restrict__ scalar_feats,
                  const float* __restrict__ W2,
                  const float* __restrict__ b2,
                  float*       __restrict__ out) {
    extern __shared__ float sm[];
    float* As  = sm;                           // [KDIM][ASTRIDE]   78336 B (swizzled cols)
    float* Bs  = As + KDIM * ASTRIDE;          // [2][8][256]       16384 B
    float* cs  = Bs + 2 * 8 * H;               // [256]
    float* w2s = cs + H;                       // [256]
    float* qp  = w2s + H;                      // [64][33]          8448 B

    int t    = threadIdx.x;
    int w    = t >> 5, lane = t & 31;
    int p0   = blockIdx.x * MTILE;

    // constants into shared
    {
        float cv = 0.f;
#pragma unroll
        for (int b = 0; b < 8; b++) cv += g_cpart[b][t];
        cs[t]  = cv;
        w2s[t] = W2[t];
    }

    // ---- Phase 1: gather. Warp w owns paths [8w, 8w+8). Per node: warp reads the
    //      full 1KB row as 2 contiguous LDG.128 (nL=4/instr). Lane holds 8 k-values. ----
    {
        int pbase = p0 + 8 * w;
        // prefetch first path's indices
        int idx[LMAX];
        int len = path_lens[pbase];
        {
            const int* nodes = path_nodes + (size_t)pbase * LMAX;
#pragma unroll
            for (int l = 0; l < LMAX; l++) idx[l] = nodes[l];
        }
        for (int pi = 0; pi < 8; pi++) {
            int cur[LMAX];
#pragma unroll
            for (int l = 0; l < LMAX; l++) cur[l] = idx[l];
            int curlen = len;
            if (pi < 7) {   // prefetch next path's metadata
                len = path_lens[pbase + pi + 1];
                const int* nodes = path_nodes + (size_t)(pbase + pi + 1) * LMAX;
#pragma unroll
                for (int l = 0; l < LMAX; l++) idx[l] = nodes[l];
            }
            float4 a0 = make_float4(0.f, 0.f, 0.f, 0.f);
            float4 a1 = make_float4(0.f, 0.f, 0.f, 0.f);
#pragma unroll
            for (int l = 0; l < LMAX; l++) {
                if (l < curlen) {
                    const float4* r = (const float4*)(node_embs + (size_t)cur[l] * H);
                    float4 v0 = r[lane];        // k in [4*lane, 4*lane+4)
                    float4 v1 = r[32 + lane];   // k in [128+4*lane, ...)
                    a0.x += v0.x; a0.y += v0.y; a0.z += v0.z; a0.w += v0.w;
                    a1.x += v1.x; a1.y += v1.y; a1.z += v1.z; a1.w += v1.w;
                }
            }
            float inv = 1.f / (float)max(curlen, 1);
            int pl = 8 * w + pi;                 // local path 0..63
            int k0 = 4 * lane, k1 = 128 + 4 * lane;
            float va0[4] = {a0.x, a0.y, a0.z, a0.w};
            float va1[4] = {a1.x, a1.y, a1.z, a1.w};
#pragma unroll
            for (int j = 0; j < 4; j++) {
                int ka = k0 + j, kb = k1 + j;
                As[ka * ASTRIDE + (pl ^ swz(ka))] = va0[j] * inv;
                As[kb * ASTRIDE + (pl ^ swz(kb))] = va1[j] * inv;
            }
        }
    }
    // edge/scalar features + zero pad rows (k = 256..287), one thread per path
    if (t < MTILE) {
        int p = p0 + t;
#pragma unroll
        for (int e = 0; e < 8; e++) {
            int k = 256 + e;
            As[k * ASTRIDE + (t ^ swz(k))] = edge_feats[p * 8 + e];
        }
#pragma unroll
        for (int f = 0; f < 16; f++) {
            int k = 264 + f;
            As[k * ASTRIDE + (t ^ swz(k))] = scalar_feats[p * 16 + f];
        }
#pragma unroll
        for (int z = 0; z < 8; z++) {
            int k = 280 + z;
            As[k * ASTRIDE + (t ^ swz(k))] = 0.f;
        }
    }

    // ---- B prologue: stage 0 (8 k-rows x 256 cols = 512 float4, 2 per thread) ----
    const float4* Wf4 = (const float4*)g_Wf;
    float4* Bs4 = (float4*)Bs;
    int f0 = 2 * t, f1 = 2 * t + 1;
    {
        float4 q0 = Wf4[f0], q1 = Wf4[f1];
        Bs4[f0] = q0; Bs4[f1] = q1;
    }
    __syncthreads();   // covers As + Bs[0]

    // ---- Phase 2: GEMM. Warp tile 32x64, micro-tile 8x8 per thread ----
    int row = ((w & 1) << 5) + ((lane & 3) << 3);          // 0..56
    int col = ((w >> 1) << 6) + ((lane >> 2) << 3);        // 0..248

    u64 acc[8][4];
#pragma unroll
    for (int i = 0; i < 8; i++)
#pragma unroll
        for (int j = 0; j < 4; j++) acc[i][j] = 0ull;

    float4 pb0, pb1;
    for (int s = 0; s < NSTAGES; s++) {
        int buf = s & 1;
        if (s + 1 < NSTAGES) {
            pb0 = Wf4[(s + 1) * 512 + f0];
            pb1 = Wf4[(s + 1) * 512 + f1];
        }
        const float* Bbuf = Bs + buf * (8 * H);
        int s4 = (s & 7) << 2;                   // swizzle constant for this k-block
        int ra = row ^ s4, rb = (row + 4) ^ s4;
#pragma unroll
        for (int kk = 0; kk < 8; kk++) {
            int kg = s * 8 + kk;
            float4 a0 = *(const float4*)&As[kg * ASTRIDE + ra];       // broadcast, 1 phase
            float4 a1 = *(const float4*)&As[kg * ASTRIDE + rb];
            ulonglong2 bA = *(const ulonglong2*)&Bbuf[kk * H + col];
            ulonglong2 bB = *(const ulonglong2*)&Bbuf[kk * H + col + 4];
            float av[8] = {a0.x, a0.y, a0.z, a0.w, a1.x, a1.y, a1.z, a1.w};
#pragma unroll
            for (int i = 0; i < 8; i++) {
                u64 ad = pack2(av[i], av[i]);
                ffma2(acc[i][0], ad, bA.x);
                ffma2(acc[i][1], ad, bA.y);
                ffma2(acc[i][2], ad, bB.x);
                ffma2(acc[i][3], ad, bB.y);
            }
        }
        if (s + 1 < NSTAGES) {
            Bs4[(buf ^ 1) * 512 + f0] = pb0;
            Bs4[(buf ^ 1) * 512 + f1] = pb1;
            __syncthreads();
        }
    }

    // ---- epilogue: +c, relu, dot(W2) partials ----
    int cgrp = col >> 3;   // 0..31, (row,cgrp) uniquely owned
#pragma unroll
    for (int i = 0; i < 8; i++) {
        float si = 0.f;
#pragma unroll
        for (int j = 0; j < 4; j++) {
            float v0, v1;
            unpack2(acc[i][j], v0, v1);
            int jg = col + 2 * j;
            v0 = fmaxf(v0 + cs[jg],     0.f);
            v1 = fmaxf(v1 + cs[jg + 1], 0.f);
            si = fmaf(v0, w2s[jg],     si);
            si = fmaf(v1, w2s[jg + 1], si);
        }
        qp[(row + i) * 33 + cgrp] = si;
    }
    __syncthreads();

    if (t < MTILE) {
        float s = b2[0];
#pragma unroll
        for (int j = 0; j < 32; j++) s += qp[t * 33 + j];
        int p = p0 + t;
        out[p] = (path_lens[p] > 0) ? s : 0.f;
    }
}

// ---------------- launch ----------------
#define FUSED_SMEM ((KDIM * ASTRIDE + 2 * 8 * H + H + H + 64 * 33) * (int)sizeof(float))

extern "C" void kernel_launch(void* const* d_in, const int* in_sizes, int n_in,
                              void* d_out, int out_size) {
    const float* node_embs    = (const float*)d_in[0];
    const int*   path_nodes   = (const int*)  d_in[1];
    const int*   path_lens    = (const int*)  d_in[2];
    const float* edge_feats   = (const float*)d_in[3];
    const float* scalar_feats = (const float*)d_in[4];
    const float* W1           = (const float*)d_in[5];
    const float* b1           = (const float*)d_in[6];
    const float* W2           = (const float*)d_in[7];
    const float* b2           = (const float*)d_in[8];
    const int*   src_idx      = (const int*)  d_in[9];
    const int*   dst_idx      = (const int*)  d_in[10];
    float* out = (float*)d_out;

    cudaFuncSetAttribute(fused_kernel,
                         cudaFuncAttributeMaxDynamicSharedMemorySize, FUSED_SMEM);

    prep_kernel<<<KDIM + 8, H>>>(W1, node_embs, b1, src_idx, dst_idx);
    fused_kernel<<<P_PATHS / MTILE, 256, FUSED_SMEM>>>(
        node_embs, path_nodes, path_lens, edge_feats, scalar_feats, W2, b2, out);
}